// round 12
// baseline (speedup 1.0000x reference)
#include <cuda_runtime.h>
#include <cuda_bf16.h>
#include <math.h>
#include <stdint.h>

#define BATCH 32
#define CH    96
#define HH    56
#define WW    56
#define HW    3136
#define CHW   301056
#define TOT   9633792
#define EPSV  1e-5f
#define NCP   48          // channel pairs

// ---------------- scratch ----------------------------------------------------
__device__ float g_h1[TOT];
__device__ float g_d [TOT];
__device__ float g_t [TOT];
__device__ uint32_t g_xlrh[BATCH * NCP * HW];
__device__ uint32_t g_xlrl[BATCH * NCP * HW];
__device__ uint32_t g_xtdh[BATCH * NCP * HW];
__device__ uint32_t g_xtdl[BATCH * NCP * HW];
__device__ uint32_t g_wh[4][CH * NCP];
__device__ uint32_t g_wl[4][CH * NCP];
__device__ float g_p1[BATCH * 25 * 2];
__device__ float g_p2[BATCH * 192 * 2];
__device__ float g_p3[BATCH * 25 * 2];

// Fast gelu: 0.5x(1+erf(x/sqrt2)) with A&S 7.1.26 erf (|eps|<=1.5e-7).
__device__ __forceinline__ float gelu_f(float x) {
    const float z = fabsf(x) * 0.7071067811865476f;
    const float t = __fdividef(1.0f, 1.0f + 0.3275911f * z);
    const float e = __expf(-z * z);
    float p = t * (0.254829592f + t * (-0.284496736f + t * (1.421413741f +
              t * (-1.453152027f + t * 1.061405429f))));
    float er = 1.0f - p * e;
    er = copysignf(er, x);
    return 0.5f * x * (1.0f + er);
}

__device__ __forceinline__ uint32_t pack2(float lo, float hi) {
    __nv_bfloat162 t = __floats2bfloat162_rn(lo, hi);
    return *(uint32_t*)&t;
}

// split (a,b) fp32 pair into bf16x2 hi word + bf16x2 lo (residual) word
__device__ __forceinline__ void split2(float a, float b, uint32_t& h, uint32_t& l) {
    __nv_bfloat162 t = __floats2bfloat162_rn(a, b);
    h = *(uint32_t*)&t;
    l = pack2(a - __bfloat162float(t.x), b - __bfloat162float(t.y));
}

__device__ __forceinline__ void mma16816(float& d0, float& d1, float& d2, float& d3,
                                         uint32_t a0, uint32_t a1, uint32_t a2, uint32_t a3,
                                         uint32_t b0, uint32_t b1) {
    asm volatile(
        "mma.sync.aligned.m16n8k16.row.col.f32.bf16.bf16.f32 "
        "{%0,%1,%2,%3}, {%4,%5,%6,%7}, {%8,%9}, {%0,%1,%2,%3};"
        : "+f"(d0), "+f"(d1), "+f"(d2), "+f"(d3)
        : "r"(a0), "r"(a1), "r"(a2), "r"(a3), "r"(b0), "r"(b1));
}

__device__ __forceinline__ void ldsm_x4(uint32_t& r0, uint32_t& r1,
                                        uint32_t& r2, uint32_t& r3, uint32_t addr) {
    asm volatile("ldmatrix.sync.aligned.m8n8.x4.shared.b16 {%0,%1,%2,%3}, [%4];"
                 : "=r"(r0), "=r"(r1), "=r"(r2), "=r"(r3) : "r"(addr));
}

__device__ __forceinline__ uint32_t smem_addr(const void* p) {
    return (uint32_t)__cvta_generic_to_shared(p);
}

// warp-0 inline GN stats from npart (sum,sumsq) pairs -> red[0]=mu, red[1]=rstd
__device__ __forceinline__ void stats_warp0(const float* __restrict__ part,
                                            int b, int npart, int warp, int lane,
                                            float* red) {
    if (warp == 0) {
        float s1 = 0.f, s2 = 0.f;
        for (int i = lane; i < npart; i += 32) {
            s1 += part[((size_t)b * npart + i) * 2];
            s2 += part[((size_t)b * npart + i) * 2 + 1];
        }
#pragma unroll
        for (int off = 16; off > 0; off >>= 1) {
            s1 += __shfl_xor_sync(0xFFFFFFFFu, s1, off);
            s2 += __shfl_xor_sync(0xFFFFFFFFu, s2, off);
        }
        if (lane == 0) {
            float mu  = s1 / (float)CHW;
            float var = s2 / (float)CHW - mu * mu;
            red[0] = mu;
            red[1] = rsqrtf(var + EPSV);
        }
    }
    __syncthreads();
}

// ---------------- weight pre-pack: fp32 [96][96] -> hi/lo bf16x2 [96][48] ----
__global__ void __launch_bounds__(256) wpack_k(
    const float* __restrict__ w1, const float* __restrict__ w21,
    const float* __restrict__ w22, const float* __restrict__ w3)
{
    const int m = blockIdx.x;
    const float* w = (m == 0) ? w1 : (m == 1) ? w21 : (m == 2) ? w22 : w3;
    for (int i = threadIdx.x; i < CH * NCP; i += 256) {
        const int o = i / NCP, cp = i % NCP;
        uint32_t h, l;
        split2(w[o * CH + 2 * cp], w[o * CH + 2 * cp + 1], h, l);
        g_wh[m][i] = h;
        g_wl[m][i] = l;
    }
}

// A-operand fragments from packed weights
__device__ __forceinline__ void load_afrags_packed(
    const uint32_t* __restrict__ wh, const uint32_t* __restrict__ wl,
    int o_row, int tig, uint32_t aH[6][4], uint32_t aL[6][4]) {
#pragma unroll
    for (int s = 0; s < 6; s++) {
#pragma unroll
        for (int q = 0; q < 4; q++) {
            const int o  = o_row + ((q & 1) ? 8 : 0);
            const int cp = s * 8 + tig + ((q & 2) ? 4 : 0);
            aH[s][q] = __ldg(&wh[o * NCP + cp]);
            aL[s][q] = __ldg(&wl[o * NCP + cp]);
        }
    }
}

#define BSTR 104   // elements per B row (52 words; conflict-free ldmatrix phases)

// ---------------- 96x96 conv1x1 (mma.sync, split-bf16, ldmatrix B) -----------
// Each CTA handles pixel tile blockIdx.x for batches blockIdx.y and +16.
// INM: 0 fp32 in; 1 packed bf16 hi/lo planes (in=hi, inl=lo); 2 gn-affine fp32.
// OUTM: 1 = gelu. PART: emit partials. ACC: += existing out.
template<int INM, int OUTM, int PART, int ACC>
__global__ void __launch_bounds__(192, 4) gemm_mma(
    const float* __restrict__ in, const uint32_t* __restrict__ inl,
    const uint32_t* __restrict__ wh, const uint32_t* __restrict__ wl,
    const float* __restrict__ bias, float* __restrict__ out,
    const float* __restrict__ part_in, const float* __restrict__ gw,
    const float* __restrict__ gb, float* __restrict__ part)
{
    extern __shared__ char dsm[];
    __nv_bfloat16* bhm = (__nv_bfloat16*)dsm;            // [128][104] hi
    __nv_bfloat16* blm = bhm + 128 * BSTR;               // [128][104] lo
    uint32_t* bh32 = (uint32_t*)bhm;
    uint32_t* bl32 = (uint32_t*)blm;
    float* red = (float*)(dsm + 128 * BSTR * 2 * 2);

    const int p0   = blockIdx.x * 128;
    const int tid  = threadIdx.x;
    const int warp = tid >> 5, lane = tid & 31;
    const int gid  = lane >> 2, tig = lane & 3;
    const int o0   = warp * 16;

    uint32_t aH[6][4], aL[6][4];
    load_afrags_packed(wh, wl, o0 + gid, tig, aH, aL);

    const float bias0 = bias[o0 + gid];
    const float bias1 = bias[o0 + gid + 8];
    const int rL = lane & 7, mL = lane >> 3;
    const uint32_t ntstep = 8 * BSTR * 2;

    for (int bi = 0; bi < 2; bi++) {
        const int b = blockIdx.y + bi * 16;

        if (bi) __syncthreads();   // prior mainloop done before smem refill

        float mu = 0.f, rs = 0.f;
        if (INM == 2) {
            stats_warp0(part_in, b, 25, warp, lane, red);
            mu = red[0]; rs = red[1];
            __syncthreads();
        }

        // ---- B fill ------------------------------------------------------
        if (INM == 1) {
            const uint32_t* inh = (const uint32_t*)in + (size_t)b * NCP * HW + p0;
            const uint32_t* inlo = inl + (size_t)b * NCP * HW + p0;
            for (int i = tid; i < NCP * 128; i += 192) {
                const int px = i & 127, cp = i >> 7;
                uint32_t h = 0, l = 0;
                if (p0 + px < HW) {
                    h = inh[(size_t)cp * HW + px];
                    l = inlo[(size_t)cp * HW + px];
                }
                const int wi = px * 52 + cp;
                bh32[wi] = h;
                bl32[wi] = l;
            }
        } else {
            const float* inb = in + (size_t)b * CHW + p0;
            for (int i = tid; i < NCP * 128; i += 192) {
                const int px = i & 127, cp = i >> 7;
                const int c = cp * 2;
                float v0 = 0.f, v1 = 0.f;
                if (p0 + px < HW) {
                    v0 = inb[(size_t)c * HW + px];
                    v1 = inb[(size_t)(c + 1) * HW + px];
                }
                if (INM == 2) {
                    float a0 = rs * gw[c],     bb0 = gb[c]     - mu * a0;
                    float a1 = rs * gw[c + 1], bb1 = gb[c + 1] - mu * a1;
                    v0 = v0 * a0 + bb0;
                    v1 = v1 * a1 + bb1;
                }
                uint32_t h, l;
                split2(v0, v1, h, l);
                const int wi = px * 52 + cp;
                bh32[wi] = h;
                bl32[wi] = l;
            }
        }
        __syncthreads();

        uint32_t hadr[3], ladr[3];
#pragma unroll
        for (int g = 0; g < 3; g++) {
            const uint32_t eoff = (uint32_t)(rL * BSTR + (2 * g + (mL >> 1)) * 16 + (mL & 1) * 8);
            hadr[g] = smem_addr(bhm + eoff);
            ladr[g] = smem_addr(blm + eoff);
        }

        float s1 = 0.f, s2 = 0.f;
        float* ob = out + (size_t)b * CHW;

        for (int nt = 0; nt < 16; nt++) {
            float d0 = 0.f, d1 = 0.f, d2 = 0.f, d3 = 0.f;
#pragma unroll
            for (int g = 0; g < 3; g++) {
                uint32_t h0, h1, h2, h3, l0, l1, l2, l3;
                ldsm_x4(h0, h1, h2, h3, hadr[g]);
                ldsm_x4(l0, l1, l2, l3, ladr[g]);
                hadr[g] += ntstep;
                ladr[g] += ntstep;
                const int sa = 2 * g, sb = 2 * g + 1;
                mma16816(d0, d1, d2, d3, aH[sa][0], aH[sa][1], aH[sa][2], aH[sa][3], h0, h1);
                mma16816(d0, d1, d2, d3, aL[sa][0], aL[sa][1], aL[sa][2], aL[sa][3], h0, h1);
                mma16816(d0, d1, d2, d3, aH[sa][0], aH[sa][1], aH[sa][2], aH[sa][3], l0, l1);
                mma16816(d0, d1, d2, d3, aH[sb][0], aH[sb][1], aH[sb][2], aH[sb][3], h2, h3);
                mma16816(d0, d1, d2, d3, aL[sb][0], aL[sb][1], aL[sb][2], aL[sb][3], h2, h3);
                mma16816(d0, d1, d2, d3, aH[sb][0], aH[sb][1], aH[sb][2], aH[sb][3], l2, l3);
            }
            const int px = p0 + nt * 8 + 2 * tig;
            if (px < HW) {
                float v00 = d0 + bias0, v01 = d1 + bias0;
                float v10 = d2 + bias1, v11 = d3 + bias1;
                if (OUTM == 1) {
                    v00 = gelu_f(v00); v01 = gelu_f(v01);
                    v10 = gelu_f(v10); v11 = gelu_f(v11);
                }
                float* p00 = ob + (size_t)(o0 + gid) * HW + px;
                float* p10 = ob + (size_t)(o0 + gid + 8) * HW + px;
                if (ACC) {
                    float2 t0 = *(float2*)p00; v00 += t0.x; v01 += t0.y;
                    float2 t1 = *(float2*)p10; v10 += t1.x; v11 += t1.y;
                }
                *(float2*)p00 = make_float2(v00, v01);
                *(float2*)p10 = make_float2(v10, v11);
                if (PART) {
                    s1 += v00 + v01 + v10 + v11;
                    s2 += v00 * v00 + v01 * v01 + v10 * v10 + v11 * v11;
                }
            }
        }

        if (PART) {
#pragma unroll
            for (int off = 16; off > 0; off >>= 1) {
                s1 += __shfl_xor_sync(0xFFFFFFFFu, s1, off);
                s2 += __shfl_xor_sync(0xFFFFFFFFu, s2, off);
            }
            __syncthreads();
            if (lane == 0) { red[warp] = s1; red[8 + warp] = s2; }
            __syncthreads();
            if (tid == 0) {
                float t1 = 0.f, t2 = 0.f;
#pragma unroll
                for (int i = 0; i < 6; i++) { t1 += red[i]; t2 += red[8 + i]; }
                float* pp = part + ((size_t)b * 25 + blockIdx.x) * 2;
                pp[0] = t1; pp[1] = t2;
            }
        }
    }
}

// ---------------- depthwise 3x3, fused GN1+GELU (stats inline) ---------------
__global__ void __launch_bounds__(256) dw_k(
    const float* __restrict__ in, const float* __restrict__ part_in,
    const float* __restrict__ gw, const float* __restrict__ gb,
    const float* __restrict__ dww, const float* __restrict__ dwb,
    float* __restrict__ out, float* __restrict__ part)
{
    __shared__ float tile[30][58];
    __shared__ float red[512];
    const int rt = blockIdx.x;
    const int c  = blockIdx.y;
    const int b  = blockIdx.z;
    const int tid = threadIdx.x;
    const int warp = tid >> 5, lane = tid & 31;

    stats_warp0(part_in, b, 25, warp, lane, red);
    const float mu = red[0], rs = red[1];
    __syncthreads();

    const float a  = rs * gw[c];
    const float bb = gb[c] - mu * a;
    const float* inb = in + (size_t)(b * CH + c) * HW;
    const int r0 = rt * 28;

    for (int i = tid; i < 30 * 58; i += 256) {
        int rr = i / 58, cc = i % 58;
        int gr = r0 - 1 + rr, gc = cc - 1;
        float v = 0.f;
        if (gr >= 0 && gr < HH && gc >= 0 && gc < WW)
            v = gelu_f(inb[gr * WW + gc] * a + bb);
        tile[rr][cc] = v;
    }
    float wd[9];
#pragma unroll
    for (int i = 0; i < 9; i++) wd[i] = dww[c * 9 + i];
    const float bd = dwb[c];
    __syncthreads();

    float s1 = 0.f, s2 = 0.f;
    for (int p = tid; p < 28 * 56; p += 256) {
        int lr = p / 56, lc = p % 56;
        float accv = bd;
#pragma unroll
        for (int i = 0; i < 3; i++)
#pragma unroll
            for (int j = 0; j < 3; j++)
                accv = fmaf(wd[i * 3 + j], tile[lr + i][lc + j], accv);
        out[(size_t)(b * CH + c) * HW + (r0 + lr) * WW + lc] = accv;
        s1 += accv; s2 += accv * accv;
    }
    red[tid] = s1; red[256 + tid] = s2;
    __syncthreads();
    for (int off = 128; off > 0; off >>= 1) {
        if (tid < off) {
            red[tid] += red[tid + off];
            red[256 + tid] += red[256 + tid + off];
        }
        __syncthreads();
    }
    if (tid == 0) {
        float* pp = part + ((size_t)b * 192 + c * 2 + rt) * 2;
        pp[0] = red[0]; pp[1] = red[256];
    }
}

// ---------------- fused LIF (grid = (tiles, batch); no boundary blocks) ------
#define LIF_TPB 9408   // NCP * 14 * 14 elements per batch
__global__ void __launch_bounds__(256) lif_k(
    const float* __restrict__ in, const float* __restrict__ part_in,
    const float* __restrict__ gw, const float* __restrict__ gb,
    const float* __restrict__ tau1_p, const float* __restrict__ vth1_p,
    const float* __restrict__ tau2_p, const float* __restrict__ vth2_p,
    uint32_t* __restrict__ xlrh, uint32_t* __restrict__ xlrl,
    uint32_t* __restrict__ xtdh, uint32_t* __restrict__ xtdl)
{
    __shared__ float red[2];
    const int tid = threadIdx.x;
    const int warp = tid >> 5, lane = tid & 31;
    const int b   = blockIdx.y;
    const int idx = blockIdx.x * 256 + tid;   // within-batch index

    stats_warp0(part_in, b, 192, warp, lane, red);
    const float mu = red[0], rs = red[1];
    if (idx >= LIF_TPB) return;

    const int wg = idx % 14;
    const int hg = (idx / 14) % 14;
    const int cp = idx / 196;

    const int c0 = 2 * cp, c1 = 2 * cp + 1;
    const float a0 = rs * gw[c0], bb0 = gb[c0] - mu * a0;
    const float a1 = rs * gw[c1], bb1 = gb[c1] - mu * a1;
    const float tau1 = tau1_p[0], vth1 = vth1_p[0];
    const float tau2 = tau2_p[0], vth2 = vth2_p[0];

    const size_t inb0 = (size_t)(b * CH + c0) * HW + (size_t)(hg * 4) * WW + wg * 4;
    const size_t ub   = (size_t)(b * NCP + cp) * HW + (size_t)(hg * 4) * WW + wg * 4;

    float gA[4][4], gB[4][4];
#pragma unroll
    for (int i = 0; i < 4; i++) {
        float4 vA = *(const float4*)(in + inb0 + (size_t)i * WW);
        float4 vB = *(const float4*)(in + inb0 + HW + (size_t)i * WW);
        gA[i][0] = gelu_f(vA.x * a0 + bb0); gA[i][1] = gelu_f(vA.y * a0 + bb0);
        gA[i][2] = gelu_f(vA.z * a0 + bb0); gA[i][3] = gelu_f(vA.w * a0 + bb0);
        gB[i][0] = gelu_f(vB.x * a1 + bb1); gB[i][1] = gelu_f(vB.y * a1 + bb1);
        gB[i][2] = gelu_f(vB.z * a1 + bb1); gB[i][3] = gelu_f(vB.w * a1 + bb1);
    }

    // W-scan (axis=3) both channels, pack + store per row
#pragma unroll
    for (int i = 0; i < 4; i++) {
        float uA = 0.f, sA = 0.f, uB = 0.f, sB = 0.f;
        uint32_t hv[4], lv[4];
#pragma unroll
        for (int j = 0; j < 4; j++) {
            uA = gA[i][j] + tau2 * uA * (1.f - sA);
            sA = (uA > vth2) ? 1.f : 0.f;
            uB = gB[i][j] + tau2 * uB * (1.f - sB);
            sB = (uB > vth2) ? 1.f : 0.f;
            split2(uA * sA, uB * sB, hv[j], lv[j]);
        }
        *(uint4*)(xtdh + ub + (size_t)i * WW) = make_uint4(hv[0], hv[1], hv[2], hv[3]);
        *(uint4*)(xtdl + ub + (size_t)i * WW) = make_uint4(lv[0], lv[1], lv[2], lv[3]);
    }

    // H-scan (axis=2) both channels
    float yA[4][4], yB[4][4];
#pragma unroll
    for (int j = 0; j < 4; j++) {
        float uA = 0.f, sA = 0.f, uB = 0.f, sB = 0.f;
#pragma unroll
        for (int i = 0; i < 4; i++) {
            uA = gA[i][j] + tau1 * uA * (1.f - sA);
            sA = (uA > vth1) ? 1.f : 0.f;
            yA[i][j] = uA * sA;
            uB = gB[i][j] + tau1 * uB * (1.f - sB);
            sB = (uB > vth1) ? 1.f : 0.f;
            yB[i][j] = uB * sB;
        }
    }
#pragma unroll
    for (int i = 0; i < 4; i++) {
        uint32_t hv[4], lv[4];
#pragma unroll
        for (int j = 0; j < 4; j++) split2(yA[i][j], yB[i][j], hv[j], lv[j]);
        *(uint4*)(xlrh + ub + (size_t)i * WW) = make_uint4(hv[0], hv[1], hv[2], hv[3]);
        *(uint4*)(xlrl + ub + (size_t)i * WW) = make_uint4(lv[0], lv[1], lv[2], lv[3]);
    }
}

// ---------------- host pipeline (7 launches) ---------------------------------
#define GEMM_SMEM (128 * BSTR * 2 * 2 + 256)

extern "C" void kernel_launch(void* const* d_in, const int* in_sizes, int n_in,
                              void* d_out, int out_size)
{
    const float* x    = (const float*)d_in[0];
    const float* w1   = (const float*)d_in[1];
    const float* b1   = (const float*)d_in[2];
    const float* n1w  = (const float*)d_in[3];
    const float* n1b  = (const float*)d_in[4];
    const float* dww  = (const float*)d_in[5];
    const float* dwb  = (const float*)d_in[6];
    const float* n2w  = (const float*)d_in[7];
    const float* n2b  = (const float*)d_in[8];
    const float* tau1 = (const float*)d_in[9];
    const float* vth1 = (const float*)d_in[10];
    const float* tau2 = (const float*)d_in[11];
    const float* vth2 = (const float*)d_in[12];
    const float* w21  = (const float*)d_in[13];
    const float* b21  = (const float*)d_in[14];
    const float* w22  = (const float*)d_in[15];
    const float* b22  = (const float*)d_in[16];
    const float* n3w  = (const float*)d_in[17];
    const float* n3b  = (const float*)d_in[18];
    const float* w3   = (const float*)d_in[19];
    const float* b3   = (const float*)d_in[20];
    float* out = (float*)d_out;

    float *h1, *dd, *tt, *p1, *p2, *p3;
    uint32_t *xlrh, *xlrl, *xtdh, *xtdl, *whb, *wlb;
    cudaGetSymbolAddress((void**)&h1,  g_h1);
    cudaGetSymbolAddress((void**)&dd,  g_d);
    cudaGetSymbolAddress((void**)&tt,  g_t);
    cudaGetSymbolAddress((void**)&xlrh, g_xlrh);
    cudaGetSymbolAddress((void**)&xlrl, g_xlrl);
    cudaGetSymbolAddress((void**)&xtdh, g_xtdh);
    cudaGetSymbolAddress((void**)&xtdl, g_xtdl);
    cudaGetSymbolAddress((void**)&whb, g_wh);
    cudaGetSymbolAddress((void**)&wlb, g_wl);
    cudaGetSymbolAddress((void**)&p1,  g_p1);
    cudaGetSymbolAddress((void**)&p2,  g_p2);
    cudaGetSymbolAddress((void**)&p3,  g_p3);

    cudaFuncSetAttribute(gemm_mma<0,0,1,0>, cudaFuncAttributeMaxDynamicSharedMemorySize, GEMM_SMEM);
    cudaFuncSetAttribute(gemm_mma<1,1,0,0>, cudaFuncAttributeMaxDynamicSharedMemorySize, GEMM_SMEM);
    cudaFuncSetAttribute(gemm_mma<1,1,1,1>, cudaFuncAttributeMaxDynamicSharedMemorySize, GEMM_SMEM);
    cudaFuncSetAttribute(gemm_mma<2,0,0,0>, cudaFuncAttributeMaxDynamicSharedMemorySize, GEMM_SMEM);

    dim3 gg(25, 16);    // 2 batches per CTA
    const int WSZ = CH * NCP;

    // 0. pack all 4 weight matrices to bf16 hi/lo
    wpack_k<<<4, 256>>>(w1, w21, w22, w3);

    // 1. conv1 -> h1, GN1 partials
    gemm_mma<0,0,1,0><<<gg, 192, GEMM_SMEM>>>(x, nullptr, whb, wlb, b1, h1,
                                              nullptr, nullptr, nullptr, p1);

    // 2. gelu(gn1(h1)) -> dwconv -> dd, GN2 partials (GN1 stats inline)
    dw_k<<<dim3(2, CH, BATCH), 256>>>(h1, p1, n1w, n1b, dww, dwb, dd, p2);

    // 3. fused LIF (GN2 stats inline) -> packed bf16 hi/lo xlr, xtd
    lif_k<<<dim3((LIF_TPB + 255) / 256, BATCH), 256>>>(
        dd, p2, n2w, n2b, tau1, vth1, tau2, vth2, xlrh, xlrl, xtdh, xtdl);

    // 4. tt = gelu(w21@xlr+b21)   (packed input)
    gemm_mma<1,1,0,0><<<gg, 192, GEMM_SMEM>>>((const float*)xlrh, xlrl,
                                              whb + WSZ, wlb + WSZ, b21, tt,
                                              nullptr, nullptr, nullptr, nullptr);

    // 5. tt += gelu(w22@xtd+b22), GN3 partials   (packed input)
    gemm_mma<1,1,1,1><<<gg, 192, GEMM_SMEM>>>((const float*)xtdh, xtdl,
                                              whb + 2 * WSZ, wlb + 2 * WSZ, b22, tt,
                                              nullptr, nullptr, nullptr, p3);

    // 6. out = conv3 @ gn3(tt)  (GN3 stats inline)
    gemm_mma<2,0,0,0><<<gg, 192, GEMM_SMEM>>>(tt, nullptr, whb + 3 * WSZ, wlb + 3 * WSZ,
                                              b3, out, p3, n3w, n3b, nullptr);
}

// round 13
// speedup vs baseline: 1.1006x; 1.1006x over previous
#include <cuda_runtime.h>
#include <cuda_bf16.h>
#include <math.h>
#include <stdint.h>

#define BATCH 32
#define CH    96
#define HH    56
#define WW    56
#define HW    3136
#define CHW   301056
#define TOT   9633792
#define EPSV  1e-5f
#define NCP   48          // channel pairs

// ---------------- scratch ----------------------------------------------------
__device__ float g_h1[TOT];
__device__ float g_d [TOT];
__device__ float g_t [TOT];
__device__ uint32_t g_xlrh[BATCH * NCP * HW];
__device__ uint32_t g_xlrl[BATCH * NCP * HW];
__device__ uint32_t g_xtdh[BATCH * NCP * HW];
__device__ uint32_t g_xtdl[BATCH * NCP * HW];
__device__ uint32_t g_wh[4][CH * NCP];
__device__ uint32_t g_wl[4][CH * NCP];
__device__ float g_k1[CH];     // b3 + W3@gb3
__device__ float g_k2[CH];     // W3@gw3
__device__ float g_p1[BATCH * 25 * 2];
__device__ float g_p2[BATCH * 192 * 2];
__device__ float g_p3[BATCH * 25 * 2];

// Fast gelu: 0.5x(1+erf(x/sqrt2)) with A&S 7.1.26 erf (|eps|<=1.5e-7).
__device__ __forceinline__ float gelu_f(float x) {
    const float z = fabsf(x) * 0.7071067811865476f;
    const float t = __fdividef(1.0f, 1.0f + 0.3275911f * z);
    const float e = __expf(-z * z);
    float p = t * (0.254829592f + t * (-0.284496736f + t * (1.421413741f +
              t * (-1.453152027f + t * 1.061405429f))));
    float er = 1.0f - p * e;
    er = copysignf(er, x);
    return 0.5f * x * (1.0f + er);
}

__device__ __forceinline__ uint32_t pack2(float lo, float hi) {
    __nv_bfloat162 t = __floats2bfloat162_rn(lo, hi);
    return *(uint32_t*)&t;
}

// split (a,b) fp32 pair into bf16x2 hi word + bf16x2 lo (residual) word
__device__ __forceinline__ void split2(float a, float b, uint32_t& h, uint32_t& l) {
    __nv_bfloat162 t = __floats2bfloat162_rn(a, b);
    h = *(uint32_t*)&t;
    l = pack2(a - __bfloat162float(t.x), b - __bfloat162float(t.y));
}

__device__ __forceinline__ void mma16816(float& d0, float& d1, float& d2, float& d3,
                                         uint32_t a0, uint32_t a1, uint32_t a2, uint32_t a3,
                                         uint32_t b0, uint32_t b1) {
    asm volatile(
        "mma.sync.aligned.m16n8k16.row.col.f32.bf16.bf16.f32 "
        "{%0,%1,%2,%3}, {%4,%5,%6,%7}, {%8,%9}, {%0,%1,%2,%3};"
        : "+f"(d0), "+f"(d1), "+f"(d2), "+f"(d3)
        : "r"(a0), "r"(a1), "r"(a2), "r"(a3), "r"(b0), "r"(b1));
}

__device__ __forceinline__ void ldsm_x4(uint32_t& r0, uint32_t& r1,
                                        uint32_t& r2, uint32_t& r3, uint32_t addr) {
    asm volatile("ldmatrix.sync.aligned.m8n8.x4.shared.b16 {%0,%1,%2,%3}, [%4];"
                 : "=r"(r0), "=r"(r1), "=r"(r2), "=r"(r3) : "r"(addr));
}

__device__ __forceinline__ uint32_t smem_addr(const void* p) {
    return (uint32_t)__cvta_generic_to_shared(p);
}

// warp-0 inline GN stats from npart (sum,sumsq) pairs -> red[0]=mu, red[1]=rstd
__device__ __forceinline__ void stats_warp0(const float* __restrict__ part,
                                            int b, int npart, int warp, int lane,
                                            float* red) {
    if (warp == 0) {
        float s1 = 0.f, s2 = 0.f;
        for (int i = lane; i < npart; i += 32) {
            s1 += part[((size_t)b * npart + i) * 2];
            s2 += part[((size_t)b * npart + i) * 2 + 1];
        }
#pragma unroll
        for (int off = 16; off > 0; off >>= 1) {
            s1 += __shfl_xor_sync(0xFFFFFFFFu, s1, off);
            s2 += __shfl_xor_sync(0xFFFFFFFFu, s2, off);
        }
        if (lane == 0) {
            float mu  = s1 / (float)CHW;
            float var = s2 / (float)CHW - mu * mu;
            red[0] = mu;
            red[1] = rsqrtf(var + EPSV);
        }
    }
    __syncthreads();
}

// ---------------- weight pre-pack ------------------------------------------
// m=0..2: plain W -> hi/lo bf16x2 [96][48].
// m=3: W3 scaled by gw3 per input channel; also K1 = b3 + W3@gb3, K2 = W3@gw3.
__global__ void __launch_bounds__(256) wpack_k(
    const float* __restrict__ w1, const float* __restrict__ w21,
    const float* __restrict__ w22, const float* __restrict__ w3,
    const float* __restrict__ gw3, const float* __restrict__ gb3,
    const float* __restrict__ b3)
{
    const int m = blockIdx.x;
    const float* w = (m == 0) ? w1 : (m == 1) ? w21 : (m == 2) ? w22 : w3;
    for (int i = threadIdx.x; i < CH * NCP; i += 256) {
        const int o = i / NCP, cp = i % NCP;
        float v0 = w[o * CH + 2 * cp];
        float v1 = w[o * CH + 2 * cp + 1];
        if (m == 3) { v0 *= gw3[2 * cp]; v1 *= gw3[2 * cp + 1]; }
        uint32_t h, l;
        split2(v0, v1, h, l);
        g_wh[m][i] = h;
        g_wl[m][i] = l;
    }
    if (m == 3 && threadIdx.x < CH) {
        const int o = threadIdx.x;
        float s1 = b3[o], s2 = 0.f;
        for (int c = 0; c < CH; c++) {
            const float wv = w3[o * CH + c];
            s1 += wv * gb3[c];
            s2 += wv * gw3[c];
        }
        g_k1[o] = s1;
        g_k2[o] = s2;
    }
}

// A-operand fragments from packed weights
__device__ __forceinline__ void load_afrags_packed(
    const uint32_t* __restrict__ wh, const uint32_t* __restrict__ wl,
    int o_row, int tig, uint32_t aH[6][4], uint32_t aL[6][4]) {
#pragma unroll
    for (int s = 0; s < 6; s++) {
#pragma unroll
        for (int q = 0; q < 4; q++) {
            const int o  = o_row + ((q & 1) ? 8 : 0);
            const int cp = s * 8 + tig + ((q & 2) ? 4 : 0);
            aH[s][q] = __ldg(&wh[o * NCP + cp]);
            aL[s][q] = __ldg(&wl[o * NCP + cp]);
        }
    }
}

#define BSTR 104   // elements per B row (52 words; conflict-free ldmatrix phases)

// ---------------- 96x96 conv1x1 (mma.sync, split-bf16, ldmatrix B) -----------
// INM: 0 fp32 in; 1 packed bf16 hi/lo planes; 3 fp32 in + GN folded in epilogue
//      (k1/k2 via gw/gb slots, stats from part_in npart=25).
// OUTM: 1 = gelu. PART: emit partials. ACC: += existing out.
template<int INM, int OUTM, int PART, int ACC>
__global__ void __launch_bounds__(192, 4) gemm_mma(
    const float* __restrict__ in, const uint32_t* __restrict__ inl,
    const uint32_t* __restrict__ wh, const uint32_t* __restrict__ wl,
    const float* __restrict__ bias, float* __restrict__ out,
    const float* __restrict__ part_in, const float* __restrict__ gw,
    const float* __restrict__ gb, float* __restrict__ part)
{
    extern __shared__ char dsm[];
    __nv_bfloat16* bhm = (__nv_bfloat16*)dsm;            // [128][104] hi
    __nv_bfloat16* blm = bhm + 128 * BSTR;               // [128][104] lo
    uint32_t* bh32 = (uint32_t*)bhm;
    uint32_t* bl32 = (uint32_t*)blm;
    float* red = (float*)(dsm + 128 * BSTR * 2 * 2);

    const int b    = blockIdx.y;
    const int p0   = blockIdx.x * 128;
    const int tid  = threadIdx.x;
    const int warp = tid >> 5, lane = tid & 31;
    const int gid  = lane >> 2, tig = lane & 3;
    const int o0   = warp * 16;

    float mu = 0.f, rs = 0.f;
    if (INM == 3) {
        stats_warp0(part_in, b, 25, warp, lane, red);
        mu = red[0]; rs = red[1];
        __syncthreads();
    }

    // ---- B fill --------------------------------------------------------
    if (INM == 1) {
        const uint32_t* inh = (const uint32_t*)in + (size_t)b * NCP * HW + p0;
        const uint32_t* inlo = inl + (size_t)b * NCP * HW + p0;
        for (int i = tid; i < NCP * 128; i += 192) {
            const int px = i & 127, cp = i >> 7;
            uint32_t h = 0, l = 0;
            if (p0 + px < HW) {
                h = inh[(size_t)cp * HW + px];
                l = inlo[(size_t)cp * HW + px];
            }
            const int wi = px * 52 + cp;
            bh32[wi] = h;
            bl32[wi] = l;
        }
    } else {
        const float* inb = in + (size_t)b * CHW + p0;
        for (int i = tid; i < NCP * 128; i += 192) {
            const int px = i & 127, cp = i >> 7;
            const int c = cp * 2;
            float v0 = 0.f, v1 = 0.f;
            if (p0 + px < HW) {
                v0 = inb[(size_t)c * HW + px];
                v1 = inb[(size_t)(c + 1) * HW + px];
            }
            uint32_t h, l;
            split2(v0, v1, h, l);
            const int wi = px * 52 + cp;
            bh32[wi] = h;
            bl32[wi] = l;
        }
    }

    uint32_t aH[6][4], aL[6][4];
    load_afrags_packed(wh, wl, o0 + gid, tig, aH, aL);
    __syncthreads();

    // ldmatrix lane pointers
    const int rL = lane & 7, mL = lane >> 3;
    uint32_t hadr[3], ladr[3];
#pragma unroll
    for (int g = 0; g < 3; g++) {
        const uint32_t eoff = (uint32_t)(rL * BSTR + (2 * g + (mL >> 1)) * 16 + (mL & 1) * 8);
        hadr[g] = smem_addr(bhm + eoff);
        ladr[g] = smem_addr(blm + eoff);
    }
    const uint32_t ntstep = 8 * BSTR * 2;

    // epilogue constants
    float e0a, e0b, e1a, e1b;   // per-o affine: v = e0 + e1*d (INM3) or v = d + bias
    if (INM == 3) {
        const float mur = -mu * rs;
        e0a = gw[o0 + gid]     + mur * gb[o0 + gid];       // gw=K1, gb=K2
        e0b = gw[o0 + gid + 8] + mur * gb[o0 + gid + 8];
        e1a = rs; e1b = rs;
    } else {
        e0a = bias[o0 + gid];
        e0b = bias[o0 + gid + 8];
        e1a = 1.f; e1b = 1.f;
    }

    float s1 = 0.f, s2 = 0.f;
    float* ob = out + (size_t)b * CHW;

    for (int nt = 0; nt < 16; nt++) {
        float d0 = 0.f, d1 = 0.f, d2 = 0.f, d3 = 0.f;
#pragma unroll
        for (int g = 0; g < 3; g++) {
            uint32_t h0, h1, h2, h3, l0, l1, l2, l3;
            ldsm_x4(h0, h1, h2, h3, hadr[g]);
            ldsm_x4(l0, l1, l2, l3, ladr[g]);
            hadr[g] += ntstep;
            ladr[g] += ntstep;
            const int sa = 2 * g, sb = 2 * g + 1;
            mma16816(d0, d1, d2, d3, aH[sa][0], aH[sa][1], aH[sa][2], aH[sa][3], h0, h1);
            mma16816(d0, d1, d2, d3, aL[sa][0], aL[sa][1], aL[sa][2], aL[sa][3], h0, h1);
            mma16816(d0, d1, d2, d3, aH[sa][0], aH[sa][1], aH[sa][2], aH[sa][3], l0, l1);
            mma16816(d0, d1, d2, d3, aH[sb][0], aH[sb][1], aH[sb][2], aH[sb][3], h2, h3);
            mma16816(d0, d1, d2, d3, aL[sb][0], aL[sb][1], aL[sb][2], aL[sb][3], h2, h3);
            mma16816(d0, d1, d2, d3, aH[sb][0], aH[sb][1], aH[sb][2], aH[sb][3], l2, l3);
        }
        const int px = p0 + nt * 8 + 2 * tig;
        if (px < HW) {
            float v00 = fmaf(e1a, d0, e0a), v01 = fmaf(e1a, d1, e0a);
            float v10 = fmaf(e1b, d2, e0b), v11 = fmaf(e1b, d3, e0b);
            if (OUTM == 1) {
                v00 = gelu_f(v00); v01 = gelu_f(v01);
                v10 = gelu_f(v10); v11 = gelu_f(v11);
            }
            float* p00 = ob + (size_t)(o0 + gid) * HW + px;
            float* p10 = ob + (size_t)(o0 + gid + 8) * HW + px;
            if (ACC) {
                float2 t0 = *(float2*)p00; v00 += t0.x; v01 += t0.y;
                float2 t1 = *(float2*)p10; v10 += t1.x; v11 += t1.y;
            }
            *(float2*)p00 = make_float2(v00, v01);
            *(float2*)p10 = make_float2(v10, v11);
            if (PART) {
                s1 += v00 + v01 + v10 + v11;
                s2 += v00 * v00 + v01 * v01 + v10 * v10 + v11 * v11;
            }
        }
    }

    if (PART) {
#pragma unroll
        for (int off = 16; off > 0; off >>= 1) {
            s1 += __shfl_xor_sync(0xFFFFFFFFu, s1, off);
            s2 += __shfl_xor_sync(0xFFFFFFFFu, s2, off);
        }
        __syncthreads();
        if (lane == 0) { red[warp] = s1; red[8 + warp] = s2; }
        __syncthreads();
        if (tid == 0) {
            float t1 = 0.f, t2 = 0.f;
#pragma unroll
            for (int i = 0; i < 6; i++) { t1 += red[i]; t2 += red[8 + i]; }
            float* pp = part + ((size_t)b * gridDim.x + blockIdx.x) * 2;
            pp[0] = t1; pp[1] = t2;
        }
    }
}

// ---------------- depthwise 3x3, fused GN1+GELU (stats inline) ---------------
__global__ void __launch_bounds__(256) dw_k(
    const float* __restrict__ in, const float* __restrict__ part_in,
    const float* __restrict__ gw, const float* __restrict__ gb,
    const float* __restrict__ dww, const float* __restrict__ dwb,
    float* __restrict__ out, float* __restrict__ part)
{
    __shared__ float tile[30][58];
    __shared__ float red[512];
    const int rt = blockIdx.x;
    const int c  = blockIdx.y;
    const int b  = blockIdx.z;
    const int tid = threadIdx.x;
    const int warp = tid >> 5, lane = tid & 31;

    stats_warp0(part_in, b, 25, warp, lane, red);
    const float mu = red[0], rs = red[1];
    __syncthreads();

    const float a  = rs * gw[c];
    const float bb = gb[c] - mu * a;
    const float* inb = in + (size_t)(b * CH + c) * HW;
    const int r0 = rt * 28;

    for (int i = tid; i < 30 * 58; i += 256) {
        int rr = i / 58, cc = i % 58;
        int gr = r0 - 1 + rr, gc = cc - 1;
        float v = 0.f;
        if (gr >= 0 && gr < HH && gc >= 0 && gc < WW)
            v = gelu_f(inb[gr * WW + gc] * a + bb);
        tile[rr][cc] = v;
    }
    float wd[9];
#pragma unroll
    for (int i = 0; i < 9; i++) wd[i] = dww[c * 9 + i];
    const float bd = dwb[c];
    __syncthreads();

    float s1 = 0.f, s2 = 0.f;
    for (int p = tid; p < 28 * 56; p += 256) {
        int lr = p / 56, lc = p % 56;
        float accv = bd;
#pragma unroll
        for (int i = 0; i < 3; i++)
#pragma unroll
            for (int j = 0; j < 3; j++)
                accv = fmaf(wd[i * 3 + j], tile[lr + i][lc + j], accv);
        out[(size_t)(b * CH + c) * HW + (r0 + lr) * WW + lc] = accv;
        s1 += accv; s2 += accv * accv;
    }
    red[tid] = s1; red[256 + tid] = s2;
    __syncthreads();
    for (int off = 128; off > 0; off >>= 1) {
        if (tid < off) {
            red[tid] += red[tid + off];
            red[256 + tid] += red[256 + tid + off];
        }
        __syncthreads();
    }
    if (tid == 0) {
        float* pp = part + ((size_t)b * 192 + c * 2 + rt) * 2;
        pp[0] = red[0]; pp[1] = red[256];
    }
}

// ---------------- fused LIF (grid = (tiles, batch)) --------------------------
#define LIF_TPB 9408   // NCP * 14 * 14 elements per batch
__global__ void __launch_bounds__(256) lif_k(
    const float* __restrict__ in, const float* __restrict__ part_in,
    const float* __restrict__ gw, const float* __restrict__ gb,
    const float* __restrict__ tau1_p, const float* __restrict__ vth1_p,
    const float* __restrict__ tau2_p, const float* __restrict__ vth2_p,
    uint32_t* __restrict__ xlrh, uint32_t* __restrict__ xlrl,
    uint32_t* __restrict__ xtdh, uint32_t* __restrict__ xtdl)
{
    __shared__ float red[2];
    const int tid = threadIdx.x;
    const int warp = tid >> 5, lane = tid & 31;
    const int b   = blockIdx.y;
    const int idx = blockIdx.x * 256 + tid;

    stats_warp0(part_in, b, 192, warp, lane, red);
    const float mu = red[0], rs = red[1];
    if (idx >= LIF_TPB) return;

    const int wg = idx % 14;
    const int hg = (idx / 14) % 14;
    const int cp = idx / 196;

    const int c0 = 2 * cp, c1 = 2 * cp + 1;
    const float a0 = rs * gw[c0], bb0 = gb[c0] - mu * a0;
    const float a1 = rs * gw[c1], bb1 = gb[c1] - mu * a1;
    const float tau1 = tau1_p[0], vth1 = vth1_p[0];
    const float tau2 = tau2_p[0], vth2 = vth2_p[0];

    const size_t inb0 = (size_t)(b * CH + c0) * HW + (size_t)(hg * 4) * WW + wg * 4;
    const size_t ub   = (size_t)(b * NCP + cp) * HW + (size_t)(hg * 4) * WW + wg * 4;

    float gA[4][4], gB[4][4];
#pragma unroll
    for (int i = 0; i < 4; i++) {
        float4 vA = *(const float4*)(in + inb0 + (size_t)i * WW);
        float4 vB = *(const float4*)(in + inb0 + HW + (size_t)i * WW);
        gA[i][0] = gelu_f(vA.x * a0 + bb0); gA[i][1] = gelu_f(vA.y * a0 + bb0);
        gA[i][2] = gelu_f(vA.z * a0 + bb0); gA[i][3] = gelu_f(vA.w * a0 + bb0);
        gB[i][0] = gelu_f(vB.x * a1 + bb1); gB[i][1] = gelu_f(vB.y * a1 + bb1);
        gB[i][2] = gelu_f(vB.z * a1 + bb1); gB[i][3] = gelu_f(vB.w * a1 + bb1);
    }

#pragma unroll
    for (int i = 0; i < 4; i++) {
        float uA = 0.f, sA = 0.f, uB = 0.f, sB = 0.f;
        uint32_t hv[4], lv[4];
#pragma unroll
        for (int j = 0; j < 4; j++) {
            uA = gA[i][j] + tau2 * uA * (1.f - sA);
            sA = (uA > vth2) ? 1.f : 0.f;
            uB = gB[i][j] + tau2 * uB * (1.f - sB);
            sB = (uB > vth2) ? 1.f : 0.f;
            split2(uA * sA, uB * sB, hv[j], lv[j]);
        }
        *(uint4*)(xtdh + ub + (size_t)i * WW) = make_uint4(hv[0], hv[1], hv[2], hv[3]);
        *(uint4*)(xtdl + ub + (size_t)i * WW) = make_uint4(lv[0], lv[1], lv[2], lv[3]);
    }

    float yA[4][4], yB[4][4];
#pragma unroll
    for (int j = 0; j < 4; j++) {
        float uA = 0.f, sA = 0.f, uB = 0.f, sB = 0.f;
#pragma unroll
        for (int i = 0; i < 4; i++) {
            uA = gA[i][j] + tau1 * uA * (1.f - sA);
            sA = (uA > vth1) ? 1.f : 0.f;
            yA[i][j] = uA * sA;
            uB = gB[i][j] + tau1 * uB * (1.f - sB);
            sB = (uB > vth1) ? 1.f : 0.f;
            yB[i][j] = uB * sB;
        }
    }
#pragma unroll
    for (int i = 0; i < 4; i++) {
        uint32_t hv[4], lv[4];
#pragma unroll
        for (int j = 0; j < 4; j++) split2(yA[i][j], yB[i][j], hv[j], lv[j]);
        *(uint4*)(xlrh + ub + (size_t)i * WW) = make_uint4(hv[0], hv[1], hv[2], hv[3]);
        *(uint4*)(xlrl + ub + (size_t)i * WW) = make_uint4(lv[0], lv[1], lv[2], lv[3]);
    }
}

// ---------------- host pipeline (7 launches) ---------------------------------
#define GEMM_SMEM (128 * BSTR * 2 * 2 + 256)

extern "C" void kernel_launch(void* const* d_in, const int* in_sizes, int n_in,
                              void* d_out, int out_size)
{
    const float* x    = (const float*)d_in[0];
    const float* w1   = (const float*)d_in[1];
    const float* b1   = (const float*)d_in[2];
    const float* n1w  = (const float*)d_in[3];
    const float* n1b  = (const float*)d_in[4];
    const float* dww  = (const float*)d_in[5];
    const float* dwb  = (const float*)d_in[6];
    const float* n2w  = (const float*)d_in[7];
    const float* n2b  = (const float*)d_in[8];
    const float* tau1 = (const float*)d_in[9];
    const float* vth1 = (const float*)d_in[10];
    const float* tau2 = (const float*)d_in[11];
    const float* vth2 = (const float*)d_in[12];
    const float* w21  = (const float*)d_in[13];
    const float* b21  = (const float*)d_in[14];
    const float* w22  = (const float*)d_in[15];
    const float* b22  = (const float*)d_in[16];
    const float* n3w  = (const float*)d_in[17];
    const float* n3b  = (const float*)d_in[18];
    const float* w3   = (const float*)d_in[19];
    const float* b3   = (const float*)d_in[20];
    float* out = (float*)d_out;

    float *h1, *dd, *tt, *p1, *p2, *p3, *k1, *k2;
    uint32_t *xlrh, *xlrl, *xtdh, *xtdl, *whb, *wlb;
    cudaGetSymbolAddress((void**)&h1,  g_h1);
    cudaGetSymbolAddress((void**)&dd,  g_d);
    cudaGetSymbolAddress((void**)&tt,  g_t);
    cudaGetSymbolAddress((void**)&xlrh, g_xlrh);
    cudaGetSymbolAddress((void**)&xlrl, g_xlrl);
    cudaGetSymbolAddress((void**)&xtdh, g_xtdh);
    cudaGetSymbolAddress((void**)&xtdl, g_xtdl);
    cudaGetSymbolAddress((void**)&whb, g_wh);
    cudaGetSymbolAddress((void**)&wlb, g_wl);
    cudaGetSymbolAddress((void**)&k1,  g_k1);
    cudaGetSymbolAddress((void**)&k2,  g_k2);
    cudaGetSymbolAddress((void**)&p1,  g_p1);
    cudaGetSymbolAddress((void**)&p2,  g_p2);
    cudaGetSymbolAddress((void**)&p3,  g_p3);

    cudaFuncSetAttribute(gemm_mma<0,0,1,0>, cudaFuncAttributeMaxDynamicSharedMemorySize, GEMM_SMEM);
    cudaFuncSetAttribute(gemm_mma<1,1,0,0>, cudaFuncAttributeMaxDynamicSharedMemorySize, GEMM_SMEM);
    cudaFuncSetAttribute(gemm_mma<1,1,1,1>, cudaFuncAttributeMaxDynamicSharedMemorySize, GEMM_SMEM);
    cudaFuncSetAttribute(gemm_mma<3,0,0,0>, cudaFuncAttributeMaxDynamicSharedMemorySize, GEMM_SMEM);

    dim3 gg(25, BATCH);
    const int WSZ = CH * NCP;

    // 0. pack weights; fold GN3 into W3 (+ K1/K2)
    wpack_k<<<4, 256>>>(w1, w21, w22, w3, n3w, n3b, b3);

    // 1. conv1 -> h1, GN1 partials
    gemm_mma<0,0,1,0><<<gg, 192, GEMM_SMEM>>>(x, nullptr, whb, wlb, b1, h1,
                                              nullptr, nullptr, nullptr, p1);

    // 2. gelu(gn1(h1)) -> dwconv -> dd, GN2 partials (GN1 stats inline)
    dw_k<<<dim3(2, CH, BATCH), 256>>>(h1, p1, n1w, n1b, dww, dwb, dd, p2);

    // 3. fused LIF (GN2 stats inline) -> packed bf16 hi/lo xlr, xtd
    lif_k<<<dim3((LIF_TPB + 255) / 256, BATCH), 256>>>(
        dd, p2, n2w, n2b, tau1, vth1, tau2, vth2, xlrh, xlrl, xtdh, xtdl);

    // 4. tt = gelu(w21@xlr+b21)   (packed input)
    gemm_mma<1,1,0,0><<<gg, 192, GEMM_SMEM>>>((const float*)xlrh, xlrl,
                                              whb + WSZ, wlb + WSZ, b21, tt,
                                              nullptr, nullptr, nullptr, nullptr);

    // 5. tt += gelu(w22@xtd+b22), GN3 partials   (packed input)
    gemm_mma<1,1,1,1><<<gg, 192, GEMM_SMEM>>>((const float*)xtdh, xtdl,
                                              whb + 2 * WSZ, wlb + 2 * WSZ, b22, tt,
                                              nullptr, nullptr, nullptr, p3);

    // 6. out = (W3*gw3)@tt scaled by GN3 stats in epilogue
    gemm_mma<3,0,0,0><<<gg, 192, GEMM_SMEM>>>(tt, nullptr, whb + 3 * WSZ, wlb + 3 * WSZ,
                                              nullptr, out, p3, k1, k2, nullptr);
}